// round 1
// baseline (speedup 1.0000x reference)
#include <cuda_runtime.h>

// Problem constants (shapes are fixed by the dataset)
#define SRC_SIZE 2000000
#define TABLE_SIZE (2 * SRC_SIZE)

// 16 MB scratch: the concatenated gathered layer inputs (stage 1 output).
// __device__ global — no allocation inside kernel_launch (harness rule).
__device__ float g_layer[TABLE_SIZE];

// Stage 1: layer_inputs = concat(values_a[idx_a], values_b[idx_b])
__global__ void stage1_gather(const float* __restrict__ va,
                              const float* __restrict__ vb,
                              const int*   __restrict__ ia,
                              const int*   __restrict__ ib,
                              int src_size)
{
    int i = blockIdx.x * blockDim.x + threadIdx.x;
    if (i < src_size) {
        g_layer[i] = __ldg(&va[__ldg(&ia[i])]);
    } else if (i < 2 * src_size) {
        int j = i - src_size;
        g_layer[i] = __ldg(&vb[__ldg(&ib[j])]);
    }
}

// Stage 2: per neuron — gather 8 values from g_layer via concat_idx,
// weighted sum with the shared 8-wide weight vector, tanh.
__global__ void __launch_bounds__(256)
stage2_rule(const int4* __restrict__ cidx,   // concat_idx viewed as int4 (2 per neuron)
            const float* __restrict__ w,     // 8 weights
            float* __restrict__ out,
            int num_neurons)
{
    int t = blockIdx.x * blockDim.x + threadIdx.x;
    if (t >= num_neurons) return;

    // 8 indices = 32 bytes, fully coalesced as two int4 loads
    int4 c0 = __ldg(&cidx[2 * t]);
    int4 c1 = __ldg(&cidx[2 * t + 1]);

    // Weights: uniform broadcast loads (L1-resident after first warp)
    float w0 = __ldg(&w[0]), w1 = __ldg(&w[1]), w2 = __ldg(&w[2]), w3 = __ldg(&w[3]);
    float w4 = __ldg(&w[4]), w5 = __ldg(&w[5]), w6 = __ldg(&w[6]), w7 = __ldg(&w[7]);

    // Issue all 8 random gathers back-to-back (MLP = 8) before consuming
    float v0 = __ldg(&g_layer[c0.x]);
    float v1 = __ldg(&g_layer[c0.y]);
    float v2 = __ldg(&g_layer[c0.z]);
    float v3 = __ldg(&g_layer[c0.w]);
    float v4 = __ldg(&g_layer[c1.x]);
    float v5 = __ldg(&g_layer[c1.y]);
    float v6 = __ldg(&g_layer[c1.z]);
    float v7 = __ldg(&g_layer[c1.w]);

    float s = v0 * w0;
    s = fmaf(v1, w1, s);
    s = fmaf(v2, w2, s);
    s = fmaf(v3, w3, s);
    s = fmaf(v4, w4, s);
    s = fmaf(v5, w5, s);
    s = fmaf(v6, w6, s);
    s = fmaf(v7, w7, s);

    out[t] = tanhf(s);
}

extern "C" void kernel_launch(void* const* d_in, const int* in_sizes, int n_in,
                              void* d_out, int out_size)
{
    // metadata order: values_a, values_b, weights, idx_a, idx_b, concat_idx
    const float* va   = (const float*)d_in[0];
    const float* vb   = (const float*)d_in[1];
    const float* w    = (const float*)d_in[2];
    const int*   ia   = (const int*)d_in[3];
    const int*   ib   = (const int*)d_in[4];
    const int*   cidx = (const int*)d_in[5];
    float* out = (float*)d_out;

    int src_size    = in_sizes[0];          // 2,000,000
    int num_neurons = out_size;             // 4,000,000

    {
        int total = 2 * src_size;
        int threads = 256;
        int blocks = (total + threads - 1) / threads;
        stage1_gather<<<blocks, threads>>>(va, vb, ia, ib, src_size);
    }
    {
        int threads = 256;
        int blocks = (num_neurons + threads - 1) / threads;
        stage2_rule<<<blocks, threads>>>((const int4*)cidx, w, out, num_neurons);
    }
}

// round 2
// speedup vs baseline: 1.0093x; 1.0093x over previous
#include <cuda_runtime.h>

// Problem constants (shapes fixed by the dataset)
#define SRC_SIZE 2000000
#define TABLE_SIZE (2 * SRC_SIZE)

// 16 MB scratch: concatenated gathered layer inputs (stage 1 output).
__device__ float g_layer[TABLE_SIZE];

// Per-slot weights, broadcast to all neurons. Read via constant port (LDC),
// keeping L1tex free for the gathers.
__constant__ float c_w[8];

// Stage 1: g_layer = concat(values_a[idx_a], values_b[idx_b]).
// One thread handles one a-entry and one b-entry (MLP = 2).
__global__ void __launch_bounds__(256)
stage1_gather(const float* __restrict__ va,
              const float* __restrict__ vb,
              const int*   __restrict__ ia,
              const int*   __restrict__ ib,
              int src_size)
{
    int i = blockIdx.x * blockDim.x + threadIdx.x;
    if (i >= src_size) return;
    int ja = __ldcs(&ia[i]);      // streaming: don't pollute L2
    int jb = __ldcs(&ib[i]);
    float a = __ldg(&va[ja]);     // random gathers: cached
    float b = __ldg(&vb[jb]);
    g_layer[i] = a;
    g_layer[src_size + i] = b;
}

// Stage 2: one thread per half-neuron (one int4 of concat_idx = 4 slots).
// Partial dot of 4 gathered values, pair-combine via shfl_xor, even lane
// applies tanh and stores.
__global__ void __launch_bounds__(256)
stage2_rule(const int4* __restrict__ cidx4,  // NUM_NEURONS*2 int4s
            float* __restrict__ out,
            int n4)                          // = NUM_NEURONS * 2 (multiple of 32)
{
    int t = blockIdx.x * blockDim.x + threadIdx.x;
    if (t >= n4) return;

    // Perfectly coalesced: lane l reads int4 #(warp_base + l). Streaming hint
    // so the 128 MB index stream doesn't evict the 16 MB table from L2.
    int4 c = __ldcs(&cidx4[t]);

    // Which half of the neuron this int4 covers (t even -> slots 0..3).
    int h = (t & 1) << 2;

    // 4 independent random gathers (issued back-to-back, MLP = 4)
    float v0 = __ldg(&g_layer[c.x]);
    float v1 = __ldg(&g_layer[c.y]);
    float v2 = __ldg(&g_layer[c.z]);
    float v3 = __ldg(&g_layer[c.w]);

    float p = v0 * c_w[h + 0];
    p = fmaf(v1, c_w[h + 1], p);
    p = fmaf(v2, c_w[h + 2], p);
    p = fmaf(v3, c_w[h + 3], p);

    // Combine the two halves of the neuron (lanes l and l^1).
    float s = p + __shfl_xor_sync(0xffffffffu, p, 1);

    // Even lane owns the neuron. Stores: lanes 0,2,..,30 -> 16 consecutive
    // floats per warp, streaming (output is never re-read).
    if ((t & 1) == 0)
        __stcs(&out[t >> 1], tanhf(s));
}

extern "C" void kernel_launch(void* const* d_in, const int* in_sizes, int n_in,
                              void* d_out, int out_size)
{
    // metadata order: values_a, values_b, weights, idx_a, idx_b, concat_idx
    const float* va   = (const float*)d_in[0];
    const float* vb   = (const float*)d_in[1];
    const float* w    = (const float*)d_in[2];
    const int*   ia   = (const int*)d_in[3];
    const int*   ib   = (const int*)d_in[4];
    const int*   cidx = (const int*)d_in[5];
    float* out = (float*)d_out;

    int src_size    = in_sizes[0];      // 2,000,000
    int num_neurons = out_size;         // 4,000,000

    // Weights into constant bank (D2D async copy: graph-capturable, no alloc).
    cudaMemcpyToSymbolAsync(c_w, w, 8 * sizeof(float), 0,
                            cudaMemcpyDeviceToDevice, 0);

    {
        int threads = 256;
        int blocks = (src_size + threads - 1) / threads;
        stage1_gather<<<blocks, threads>>>(va, vb, ia, ib, src_size);
    }
    {
        int n4 = num_neurons * 2;       // one thread per int4 (half-neuron)
        int threads = 256;
        int blocks = (n4 + threads - 1) / threads;
        stage2_rule<<<blocks, threads>>>((const int4*)cidx, out, n4);
    }
}

// round 3
// speedup vs baseline: 1.0261x; 1.0167x over previous
#include <cuda_runtime.h>

// Problem constants (shapes fixed by the dataset)
#define SRC_SIZE 2000000
#define TABLE_SIZE (2 * SRC_SIZE)

// 16 MB scratch: concatenated gathered layer inputs (stage 1 output).
__device__ float g_layer[TABLE_SIZE];

// Per-slot weights in constant bank (LDC path, off L1tex).
__constant__ float c_w[8];

// L2-only load (bypass L1 allocation): random gathers never hit L1 anyway
// (16 MB table vs 228 KB L1), so skip the fill/evict work.
__device__ __forceinline__ float ldcg_f(const float* p) { return __ldcg(p); }

// Stage 1: g_layer = concat(values_a[idx_a], values_b[idx_b]).
// One thread handles 2 consecutive a-entries and 2 b-entries (MLP = 4).
__global__ void __launch_bounds__(256)
stage1_gather(const float* __restrict__ va,
              const float* __restrict__ vb,
              const int2*  __restrict__ ia2,
              const int2*  __restrict__ ib2,
              int half)                       // = src_size / 2
{
    int i = blockIdx.x * blockDim.x + threadIdx.x;
    if (i >= half) return;

    int2 ja = __ldcs(&ia2[i]);                // coalesced streaming idx reads
    int2 jb = __ldcs(&ib2[i]);

    // 4 independent random gathers, L2-only
    float a0 = ldcg_f(&va[ja.x]);
    float a1 = ldcg_f(&va[ja.y]);
    float b0 = ldcg_f(&vb[jb.x]);
    float b1 = ldcg_f(&vb[jb.y]);

    float2* outa = (float2*)g_layer;
    float2* outb = (float2*)(g_layer + 2 * half);
    outa[i] = make_float2(a0, a1);
    outb[i] = make_float2(b0, b1);
}

// Stage 2: one thread per half-neuron (one int4 of concat_idx = 4 slots).
__global__ void __launch_bounds__(256)
stage2_rule(const int4* __restrict__ cidx4,   // NUM_NEURONS*2 int4s
            float* __restrict__ out,
            int n4)                           // = NUM_NEURONS * 2
{
    int t = blockIdx.x * blockDim.x + threadIdx.x;
    if (t >= n4) return;

    // Coalesced streaming read of 4 indices
    int4 c = __ldcs(&cidx4[t]);

    int h = (t & 1) << 2;                     // slot offset 0 or 4

    // 4 independent random gathers, L2-only (no L1 allocate)
    float v0 = ldcg_f(&g_layer[c.x]);
    float v1 = ldcg_f(&g_layer[c.y]);
    float v2 = ldcg_f(&g_layer[c.z]);
    float v3 = ldcg_f(&g_layer[c.w]);

    float p = v0 * c_w[h + 0];
    p = fmaf(v1, c_w[h + 1], p);
    p = fmaf(v2, c_w[h + 2], p);
    p = fmaf(v3, c_w[h + 3], p);

    // Combine the two halves of the neuron (lanes l and l^1)
    float s = p + __shfl_xor_sync(0xffffffffu, p, 1);

    if ((t & 1) == 0)
        __stcs(&out[t >> 1], tanhf(s));
}

extern "C" void kernel_launch(void* const* d_in, const int* in_sizes, int n_in,
                              void* d_out, int out_size)
{
    // metadata order: values_a, values_b, weights, idx_a, idx_b, concat_idx
    const float* va   = (const float*)d_in[0];
    const float* vb   = (const float*)d_in[1];
    const float* w    = (const float*)d_in[2];
    const int*   ia   = (const int*)d_in[3];
    const int*   ib   = (const int*)d_in[4];
    const int*   cidx = (const int*)d_in[5];
    float* out = (float*)d_out;

    int src_size    = in_sizes[0];      // 2,000,000 (even)
    int num_neurons = out_size;         // 4,000,000

    cudaMemcpyToSymbolAsync(c_w, w, 8 * sizeof(float), 0,
                            cudaMemcpyDeviceToDevice, 0);

    {
        int half = src_size / 2;
        int threads = 256;
        int blocks = (half + threads - 1) / threads;
        stage1_gather<<<blocks, threads>>>(va, vb,
                                           (const int2*)ia, (const int2*)ib,
                                           half);
    }
    {
        int n4 = num_neurons * 2;       // one thread per int4 (half-neuron)
        int threads = 256;
        int blocks = (n4 + threads - 1) / threads;
        stage2_rule<<<blocks, threads>>>((const int4*)cidx, out, n4);
    }
}

// round 4
// speedup vs baseline: 1.0406x; 1.0141x over previous
#include <cuda_runtime.h>

// Problem constants (shapes fixed by the dataset)
#define SRC_SIZE 2000000
#define TABLE_SIZE (2 * SRC_SIZE)

// 16 MB scratch: concatenated gathered layer inputs (stage 1 output).
__device__ float g_layer[TABLE_SIZE];

// Stage 1: g_layer = concat(values_a[idx_a], values_b[idx_b]).
// One thread handles 4 consecutive a-entries and 4 b-entries (MLP = 8).
__global__ void __launch_bounds__(256)
stage1_gather(const float* __restrict__ va,
              const float* __restrict__ vb,
              const int4*  __restrict__ ia4,
              const int4*  __restrict__ ib4,
              int quarter)                    // = src_size / 4
{
    int i = blockIdx.x * blockDim.x + threadIdx.x;
    if (i >= quarter) return;

    int4 ja = __ldcs(&ia4[i]);                // coalesced streaming idx reads
    int4 jb = __ldcs(&ib4[i]);

    // 8 independent random gathers in flight
    float a0 = __ldcg(&va[ja.x]);
    float a1 = __ldcg(&va[ja.y]);
    float a2 = __ldcg(&va[ja.z]);
    float a3 = __ldcg(&va[ja.w]);
    float b0 = __ldcg(&vb[jb.x]);
    float b1 = __ldcg(&vb[jb.y]);
    float b2 = __ldcg(&vb[jb.z]);
    float b3 = __ldcg(&vb[jb.w]);

    float4* outa = (float4*)g_layer;
    float4* outb = (float4*)(g_layer + 4 * quarter);
    outa[i] = make_float4(a0, a1, a2, a3);
    outb[i] = make_float4(b0, b1, b2, b3);
}

// Stage 2: one thread per neuron — 8 random gathers, weighted sum, tanh.
// Pinned at the L1tex wavefront floor (32M wavefronts chip-wide).
__global__ void __launch_bounds__(256)
stage2_rule(const int4* __restrict__ cidx4,   // 2 int4s per neuron
            const float* __restrict__ w,      // 8 weights (L1-resident broadcast)
            float* __restrict__ out,
            int num_neurons)
{
    int t = blockIdx.x * blockDim.x + threadIdx.x;
    if (t >= num_neurons) return;

    // 32B of indices per thread, coalesced, streaming (protect table in L2)
    int4 c0 = __ldcs(&cidx4[2 * t]);
    int4 c1 = __ldcs(&cidx4[2 * t + 1]);

    float w0 = __ldg(&w[0]), w1 = __ldg(&w[1]), w2 = __ldg(&w[2]), w3 = __ldg(&w[3]);
    float w4 = __ldg(&w[4]), w5 = __ldg(&w[5]), w6 = __ldg(&w[6]), w7 = __ldg(&w[7]);

    // 8 independent random gathers (MLP = 8), L2-only
    float v0 = __ldcg(&g_layer[c0.x]);
    float v1 = __ldcg(&g_layer[c0.y]);
    float v2 = __ldcg(&g_layer[c0.z]);
    float v3 = __ldcg(&g_layer[c0.w]);
    float v4 = __ldcg(&g_layer[c1.x]);
    float v5 = __ldcg(&g_layer[c1.y]);
    float v6 = __ldcg(&g_layer[c1.z]);
    float v7 = __ldcg(&g_layer[c1.w]);

    float s = v0 * w0;
    s = fmaf(v1, w1, s);
    s = fmaf(v2, w2, s);
    s = fmaf(v3, w3, s);
    s = fmaf(v4, w4, s);
    s = fmaf(v5, w5, s);
    s = fmaf(v6, w6, s);
    s = fmaf(v7, w7, s);

    __stcs(&out[t], tanhf(s));
}

extern "C" void kernel_launch(void* const* d_in, const int* in_sizes, int n_in,
                              void* d_out, int out_size)
{
    // metadata order: values_a, values_b, weights, idx_a, idx_b, concat_idx
    const float* va   = (const float*)d_in[0];
    const float* vb   = (const float*)d_in[1];
    const float* w    = (const float*)d_in[2];
    const int*   ia   = (const int*)d_in[3];
    const int*   ib   = (const int*)d_in[4];
    const int*   cidx = (const int*)d_in[5];
    float* out = (float*)d_out;

    int src_size    = in_sizes[0];      // 2,000,000 (divisible by 4)
    int num_neurons = out_size;         // 4,000,000

    {
        int quarter = src_size / 4;
        int threads = 256;
        int blocks = (quarter + threads - 1) / threads;
        stage1_gather<<<blocks, threads>>>(va, vb,
                                           (const int4*)ia, (const int4*)ib,
                                           quarter);
    }
    {
        int threads = 256;
        int blocks = (num_neurons + threads - 1) / threads;
        stage2_rule<<<blocks, threads>>>((const int4*)cidx, w, out, num_neurons);
    }
}